// round 15
// baseline (speedup 1.0000x reference)
#include <cuda_runtime.h>
#include <math.h>

// Problem constants
#define BATCH 128
#define NBOX  500
#define NCLS  80
#define NLAB  79            // argmax excludes class 79
#define NHEAD 6
#define NDDIM 16            // keep+DDIM CTAs (each owns 32 rows x all batches)

// Output layout (float32): boxes_next (B,N,2) | scores (B,N) | labels (B,N) | keep (B,N)
#define OFF_SCORE (BATCH*NBOX*2)
#define OFF_LAB   (OFF_SCORE + BATCH*NBOX)
#define OFF_KEEP  (OFF_LAB + BATCH*NBOX)

#define FULLM 0xffffffffu

// order-preserving float->uint transform (bijective)
__device__ __forceinline__ unsigned ord_u(float x) {
    unsigned u = __float_as_uint(x);
    return (u & 0x80000000u) ? ~u : (u | 0x80000000u);
}

__global__ __launch_bounds__(1024, 1)
void ddet_kernel(const float* __restrict__ boxes_t,
                 const float* __restrict__ pclass,
                 const float* __restrict__ pboxes,
                 const float* __restrict__ noise,
                 const float* __restrict__ fresh,
                 const float* __restrict__ ac,
                 const int*   __restrict__ tnow_p,
                 const int*   __restrict__ tnext_p,
                 float*       __restrict__ out)
{
    const int tid  = threadIdx.x;
    const float* pc50 = pclass + (size_t)(NHEAD - 1) * BATCH * NBOX * NCLS;   // batch 0

    // ============== keep + DDIM path (CTAs 128..143), split by ROWS ==============
    // CTA k owns rows [32k, 32k+32) for ALL batches: pc50 slice read once (10 KB),
    // DDIM loads coalesced in n.
    if (blockIdx.x >= BATCH) {
        __shared__ unsigned char s_kp[32];
        const int k  = blockIdx.x - BATCH;
        const int r0 = 32 * k;

        const int   tnow  = tnow_p[0];
        const int   tnext = tnext_p[0];
        const float a     = ac[tnow];
        const float an    = ac[tnext];
        const float sr    = sqrtf(1.0f / a);
        const float srm1  = sqrtf(1.0f / a - 1.0f);
        const float san   = sqrtf(an);
        const float sg    = sqrtf((1.0f - a / an) * (1.0f - an) / (1.0f - a));
        const float ccv   = sqrtf(1.0f - an - sg * sg);

        if (tid < 32) s_kp[tid] = 0;
        __syncthreads();

        // keep[rl] = any(pc50[r0+rl, :] > 0)   (sigmoid(x)>0.5 <=> x>0)
        if (tid < 32 * 20) {
            const int rl  = tid / 20;
            const int f4  = tid - rl * 20;
            const int row = r0 + rl;
            if (row < NBOX) {
                const float4 v = ((const float4*)(pc50 + (size_t)row * NCLS))[f4];
                if (fmaxf(fmaxf(v.x, v.y), fmaxf(v.z, v.w)) > 0.0f)
                    s_kp[rl] = 1;                 // benign race, all write 1
            }
        }
        __syncthreads();

        // DDIM boxes_next: all 128 batches x this CTA's 32 rows (n-coalesced)
        for (int i = tid; i < BATCH * 32; i += 1024) {
            const int bb = i >> 5;
            const int rl = i & 31;
            const int n  = r0 + rl;
            if (n < NBOX) {
                const float* pb5b = pboxes + ((size_t)(NHEAD - 1) * BATCH + bb) * NBOX * 2;
                const float2 cw = ((const float2*)pb5b)[n];
                const float2 bt = ((const float2*)boxes_t)[bb * NBOX + n];
                const float2 nz = ((const float2*)noise)[bb * NBOX + n];
                const float2 fr = ((const float2*)fresh)[bb * NBOX + n];
                const bool keep0 = s_kp[rl];
                float2 o;
                const float pnx = (sr * bt.x - cw.x) / srm1;
                const float pny = (sr * bt.y - cw.y) / srm1;
                o.x = keep0 ? (cw.x * san + ccv * pnx + sg * nz.x) : fr.x;
                o.y = keep0 ? (cw.y * san + ccv * pny + sg * nz.y) : fr.y;
                ((float2*)out)[bb * NBOX + n] = o;
            }
        }
        return;
    }

    // ============================ batch path (CTAs 0..127) =======================
    __shared__ unsigned int   s_cnt[80];                 // label histogram
    __shared__ int            s_off[80];                 // exclusive prefix
    __shared__ unsigned long long s_kp64[NBOX];          // keyhi<<32 | bi<<16 | p
    __shared__ unsigned long long s_slot[NBOX];          // grouped keys
    __shared__ float4         s_geo[NBOX];               // {3x1,3x2,w,-} by orig idx

    const int b    = blockIdx.x;
    const int wid  = tid >> 5;
    const int lane = tid & 31;

    const float* pc5 = pclass + ((size_t)(NHEAD - 1) * BATCH + b) * NBOX * NCLS;
    const float* pb5 = pboxes + ((size_t)(NHEAD - 1) * BATCH + b) * NBOX * 2;

    if (tid < 80) s_cnt[tid] = 0;

    // prefetch box geometry input (hidden under Phase 1)
    float2 cw;
    if (tid < NBOX) cw = ((const float2*)pb5)[tid];
    __syncthreads();   // s_cnt zeroed before Phase-1 atomics

    // ====== Phase 1: softmax score + argmax label + outputs + histogram ==========
    // 4 lanes per row; lane q holds float4s {q,q+4,q+8,q+12,q+16}.
    // Chunk max = FMNMX tree (1 instr/elem); index by equality chain (first match
    // = lowest class, exact fp32 -> tie rule preserved).
    {
        const int g2 = tid >> 2;      // row group 0..255
        const int q  = tid & 3;

// full chunk: exp-sum + fmax-tree max + equality-chain index
#define FOLDX(v, cb, e, m, ix)                                              \
        e = __expf(v.x) + __expf(v.y) + __expf(v.z) + __expf(v.w);          \
        m = fmaxf(fmaxf(v.x, v.y), fmaxf(v.z, v.w));                        \
        ix = (v.x == m) ? (cb)                                              \
           : (v.y == m) ? (cb) + 1                                         \
           : (v.z == m) ? (cb) + 2 : (cb) + 3;
// last chunk: element .w is class 67+4q (==79 when q==3) -> exclude from max
#define FOLDXL(v, cb, e, m, ix)                                             \
        e = __expf(v.x) + __expf(v.y) + __expf(v.z) + __expf(v.w);          \
        m = fmaxf(fmaxf(v.x, v.y), v.z);                                    \
        if (q < 3) m = fmaxf(m, v.w);                                       \
        ix = (v.x == m) ? (cb)                                              \
           : (v.y == m) ? (cb) + 1                                         \
           : (v.z == m) ? (cb) + 2 : (cb) + 3;

        #pragma unroll
        for (int pass = 0; pass < 2; pass++) {
            const int rowR = g2 + 256 * pass;
            const bool wr  = (rowR < NBOX);
            const int row  = wr ? rowR : (NBOX - 1);

            const float4* rp = (const float4*)(pc5 + (size_t)row * NCLS);
            const float4 v0 = rp[q],      v1 = rp[q + 4],  v2 = rp[q + 8];
            const float4 v3 = rp[q + 12], v4 = rp[q + 16];

            const int c0 = 4 * q;
            float e0, e1, e2, e3, e4;
            float m0, m1, m2, m3, m4;
            int   i0, i1, i2, i3, i4;
            FOLDX (v0, c0,      e0, m0, i0)
            FOLDX (v1, c0 + 16, e1, m1, i1)
            FOLDX (v2, c0 + 32, e2, m2, i2)
            FOLDX (v3, c0 + 48, e3, m3, i3)
            FOLDXL(v4, c0 + 64, e4, m4, i4)

            float e = (e0 + e1) + (e2 + e3) + e4;
            // chunk merge, ascending: strict > keeps lower class on ties
            float best = m0; int bi = i0;
            if (m1 > best) { best = m1; bi = i1; }
            if (m2 > best) { best = m2; bi = i2; }
            if (m3 > best) { best = m3; bi = i3; }
            if (m4 > best) { best = m4; bi = i4; }

            // merge the 4 lanes of the row
            #pragma unroll
            for (int off = 1; off <= 2; off <<= 1) {
                const float e2m = __shfl_xor_sync(FULLM, e,    off);
                const float b2  = __shfl_xor_sync(FULLM, best, off);
                const int   bi2 = __shfl_xor_sync(FULLM, bi,   off);
                e += e2m;
                if (b2 > best || (b2 == best && bi2 < bi)) { best = b2; bi = bi2; }
            }
            if (q == 0 && wr) {
                const float score = __fdividef(__expf(best), e);
                out[OFF_SCORE + b * NBOX + row] = score;
                out[OFF_LAB   + b * NBOX + row] = (float)bi;
                const unsigned p = atomicAdd(&s_cnt[bi], 1u);
                // single 64-bit store: key-hi | label | arrival rank
                s_kp64[row] = ((unsigned long long)(~ord_u(score)) << 32)
                            | ((unsigned long long)(unsigned)bi << 16)
                            | (unsigned long long)p;
            }
        }
#undef FOLDX
#undef FOLDXL
    }
    __syncthreads();

    // ==== Phase 2: geometry build (all threads) + 80-bin scan (warp 0), overlapped
    if (tid < NBOX) {
        // geometry scaled by 3: iou > 0.5  <=>  3*inter > wi + wj (clamps redundant)
        const float w = fmaxf(cw.y, 0.0001f);
        s_geo[tid] = make_float4(3.0f * (cw.x - 0.5f * w), 3.0f * (cw.x + 0.5f * w), w, 0.0f);
    }
    if (wid == 0) {
        const int l = lane;
        const unsigned ca = s_cnt[l];
        const unsigned cb = s_cnt[l + 32];
        const unsigned cc = (l < 16) ? s_cnt[l + 64] : 0u;
        unsigned ia = ca, ib = cb, ic = cc;
        #pragma unroll
        for (int off = 1; off <= 16; off <<= 1) {
            const unsigned ta = __shfl_up_sync(FULLM, ia, off);
            const unsigned tb = __shfl_up_sync(FULLM, ib, off);
            const unsigned tc = __shfl_up_sync(FULLM, ic, off);
            if (l >= off) { ia += ta; ib += tb; ic += tc; }
        }
        const unsigned S0 = __shfl_sync(FULLM, ia, 31);
        const unsigned S1 = __shfl_sync(FULLM, ib, 31);
        s_off[l]      = (int)(ia - ca);
        s_off[l + 32] = (int)(S0 + ib - cb);
        if (l < 16) s_off[l + 64] = (int)(S0 + S1 + ic - cc);
    }
    __syncthreads();

    // ===================== Phase 3: scatter keys into groups =====================
    if (tid < NBOX) {
        const unsigned long long kp = s_kp64[tid];
        const int lab = (int)((kp >> 16) & 0xffffu);
        const int p   = (int)(kp & 0xffffu);
        s_slot[s_off[lab] + p] =
            (kp & 0xffffffff00000000ULL) | (unsigned)tid;
    }
    __syncthreads();

    // ========= Phase 4: warp-parallel per-label NMS (lane = rank) ================
    for (int l = wid; l < NLAB; l += 32) {
        const int g = (int)s_cnt[l];
        if (g == 0) continue;
        const int base = s_off[l];
        if (g <= 32) {
            unsigned long long k =
                (lane < g) ? s_slot[base + lane] : 0xffffffffffffffffULL;
            int rank = 0;
            for (int i = 0; i < g; i++)                      // independent shfls
                rank += (__shfl_sync(FULLM, k, i) < k);
            // physically reorder so lane r holds the rank-r element
            if (lane < g) s_slot[base + rank] = k;
            __syncwarp();
            int idx = 0;
            float4 bx = make_float4(1e30f, -1e30f, 0.0f, 0.0f);   // never overlaps
            if (lane < g) {
                const unsigned long long k2 = s_slot[base + lane];
                idx = (int)(k2 & 0xffffffffu);
                bx  = s_geo[idx];
            }
            // candidate-suppressor bits: i < lane that overlaps me
            unsigned cand = 0;
            for (int i = 0; i < g; i++) {                    // independent shfls
                const float hx1 = __shfl_sync(FULLM, bx.x, i);
                const float hx2 = __shfl_sync(FULLM, bx.y, i);
                const float hw  = __shfl_sync(FULLM, bx.z, i);
                const float t = fminf(hx2, bx.y) - fmaxf(hx1, bx.x);
                if (lane > i && t > hw + bx.z) cand |= 1u << i;
            }
            // greedy resolve: ballots depend only on cand (pipelined); ALU carry
            unsigned sup = 0;
            for (int i = 0; i < g; i++) {
                const unsigned mi = __ballot_sync(FULLM, (cand >> i) & 1u);
                if (!((sup >> i) & 1u)) sup |= mi;
            }
            if (lane < g)
                out[OFF_KEEP + b * NBOX + idx] = ((sup >> lane) & 1u) ? 0.0f : 1.0f;
        } else if (lane == 0) {
            // serial fallback (groups > 32: vanishingly rare)
            unsigned long long sup = 0;
            for (int i = 1; i < g; i++) {
                const unsigned long long kv = s_slot[base + i];
                int j = i - 1;
                while (j >= 0 && s_slot[base + j] > kv) {
                    s_slot[base + j + 1] = s_slot[base + j]; j--;
                }
                s_slot[base + j + 1] = kv;
            }
            for (int aa = 0; aa < g; aa++) {
                const bool kept = (aa >= 64) || !((sup >> aa) & 1ULL);
                const int idx = (int)(s_slot[base + aa] & 0xffffffffu);
                out[OFF_KEEP + b * NBOX + idx] = kept ? 1.0f : 0.0f;
                if (kept) {
                    const float4 ba = s_geo[idx];
                    for (int c = aa + 1; c < g && c < 64; c++) {
                        const int jdx = (int)(s_slot[base + c] & 0xffffffffu);
                        const float4 bc = s_geo[jdx];
                        const float t = fminf(ba.y, bc.y) - fmaxf(ba.x, bc.x);
                        if (t > ba.z + bc.z) sup |= 1ULL << c;
                    }
                }
            }
        }
    }
}

extern "C" void kernel_launch(void* const* d_in, const int* in_sizes, int n_in,
                              void* d_out, int out_size)
{
    const float* boxes_t = (const float*)d_in[0];
    const float* pclass  = (const float*)d_in[1];
    const float* pboxes  = (const float*)d_in[2];
    const float* noise   = (const float*)d_in[3];
    const float* fresh   = (const float*)d_in[4];
    const float* ac      = (const float*)d_in[5];
    const int*   tnow    = (const int*)d_in[6];
    const int*   tnext   = (const int*)d_in[7];
    float* out = (float*)d_out;

    ddet_kernel<<<BATCH + NDDIM, 1024>>>(boxes_t, pclass, pboxes, noise, fresh,
                                         ac, tnow, tnext, out);
}

// round 16
// speedup vs baseline: 1.0175x; 1.0175x over previous
#include <cuda_runtime.h>
#include <math.h>

// Problem constants
#define BATCH 128
#define NBOX  500
#define NCLS  80
#define NLAB  79            // argmax excludes class 79
#define NHEAD 6
#define NDDIM 16            // keep+DDIM CTAs (each owns 32 rows x all batches)

// Output layout (float32): boxes_next (B,N,2) | scores (B,N) | labels (B,N) | keep (B,N)
#define OFF_SCORE (BATCH*NBOX*2)
#define OFF_LAB   (OFF_SCORE + BATCH*NBOX)
#define OFF_KEEP  (OFF_LAB + BATCH*NBOX)

#define FULLM 0xffffffffu

// order-preserving float->uint transform (bijective)
__device__ __forceinline__ unsigned ord_u(float x) {
    unsigned u = __float_as_uint(x);
    return (u & 0x80000000u) ? ~u : (u | 0x80000000u);
}

__global__ __launch_bounds__(1024, 1)
void ddet_kernel(const float* __restrict__ boxes_t,
                 const float* __restrict__ pclass,
                 const float* __restrict__ pboxes,
                 const float* __restrict__ noise,
                 const float* __restrict__ fresh,
                 const float* __restrict__ ac,
                 const int*   __restrict__ tnow_p,
                 const int*   __restrict__ tnext_p,
                 float*       __restrict__ out)
{
    const int tid  = threadIdx.x;
    const float* pc50 = pclass + (size_t)(NHEAD - 1) * BATCH * NBOX * NCLS;   // batch 0

    // ============== keep + DDIM path (CTAs 128..143), split by ROWS ==============
    // CTA k owns rows [32k, 32k+32) for ALL batches: pc50 slice read once (10 KB),
    // DDIM loads coalesced in n.
    if (blockIdx.x >= BATCH) {
        __shared__ unsigned char s_kp[32];
        const int k  = blockIdx.x - BATCH;
        const int r0 = 32 * k;

        const int   tnow  = tnow_p[0];
        const int   tnext = tnext_p[0];
        const float a     = ac[tnow];
        const float an    = ac[tnext];
        const float sr    = sqrtf(1.0f / a);
        const float srm1  = sqrtf(1.0f / a - 1.0f);
        const float san   = sqrtf(an);
        const float sg    = sqrtf((1.0f - a / an) * (1.0f - an) / (1.0f - a));
        const float ccv   = sqrtf(1.0f - an - sg * sg);

        if (tid < 32) s_kp[tid] = 0;
        __syncthreads();

        // keep[rl] = any(pc50[r0+rl, :] > 0)   (sigmoid(x)>0.5 <=> x>0)
        if (tid < 32 * 20) {
            const int rl  = tid / 20;
            const int f4  = tid - rl * 20;
            const int row = r0 + rl;
            if (row < NBOX) {
                const float4 v = ((const float4*)(pc50 + (size_t)row * NCLS))[f4];
                if (fmaxf(fmaxf(v.x, v.y), fmaxf(v.z, v.w)) > 0.0f)
                    s_kp[rl] = 1;                 // benign race, all write 1
            }
        }
        __syncthreads();

        // DDIM boxes_next: all 128 batches x this CTA's 32 rows (n-coalesced)
        for (int i = tid; i < BATCH * 32; i += 1024) {
            const int bb = i >> 5;
            const int rl = i & 31;
            const int n  = r0 + rl;
            if (n < NBOX) {
                const float* pb5b = pboxes + ((size_t)(NHEAD - 1) * BATCH + bb) * NBOX * 2;
                const float2 cw = ((const float2*)pb5b)[n];
                const float2 bt = ((const float2*)boxes_t)[bb * NBOX + n];
                const float2 nz = ((const float2*)noise)[bb * NBOX + n];
                const float2 fr = ((const float2*)fresh)[bb * NBOX + n];
                const bool keep0 = s_kp[rl];
                float2 o;
                const float pnx = (sr * bt.x - cw.x) / srm1;
                const float pny = (sr * bt.y - cw.y) / srm1;
                o.x = keep0 ? (cw.x * san + ccv * pnx + sg * nz.x) : fr.x;
                o.y = keep0 ? (cw.y * san + ccv * pny + sg * nz.y) : fr.y;
                ((float2*)out)[bb * NBOX + n] = o;
            }
        }
        return;
    }

    // ============================ batch path (CTAs 0..127) =======================
    __shared__ unsigned int   s_cnt[80];                 // label histogram
    __shared__ int            s_off[80];                 // exclusive prefix
    __shared__ unsigned long long s_kp64[NBOX];          // keyhi<<32 | bi<<16 | p
    __shared__ unsigned long long s_slot[NBOX];          // grouped keys
    __shared__ float4         s_geo[NBOX];               // {3x1,3x2,w,-} by orig idx

    const int b    = blockIdx.x;
    const int wid  = tid >> 5;
    const int lane = tid & 31;

    const float* pc5 = pclass + ((size_t)(NHEAD - 1) * BATCH + b) * NBOX * NCLS;
    const float* pb5 = pboxes + ((size_t)(NHEAD - 1) * BATCH + b) * NBOX * 2;

    if (tid < 80) s_cnt[tid] = 0;

    // prefetch box geometry input (hidden under Phase 1)
    float2 cw;
    if (tid < NBOX) cw = ((const float2*)pb5)[tid];
    __syncthreads();   // s_cnt zeroed before Phase-1 atomics

    // ====== Phase 1: softmax score + argmax label + outputs + histogram ==========
    // 4 lanes per row; lane q holds float4s {q,q+4,q+8,q+12,q+16}.
    // Five INDEPENDENT accumulator chunks (chain depth 4), per-element tracking
    // (the codegen that measured 12.80 us in R11).
    {
        const int g2 = tid >> 2;      // row group 0..255
        const int q  = tid & 3;

// chunk fold: independent (e, m, ix); within-chunk ascending class order
#define FOLDX(v, cb, e, m, ix)                                              \
        e = __expf(v.x) + __expf(v.y) + __expf(v.z) + __expf(v.w);          \
        m = v.x; ix = (cb);                                                 \
        if (v.y > m) { m = v.y; ix = (cb) + 1; }                            \
        if (v.z > m) { m = v.z; ix = (cb) + 2; }                            \
        if (v.w > m) { m = v.w; ix = (cb) + 3; }
// last chunk: element .w is class 67+4q (==79 when q==3) -> exclude then
#define FOLDXL(v, cb, e, m, ix)                                             \
        e = __expf(v.x) + __expf(v.y) + __expf(v.z) + __expf(v.w);          \
        m = v.x; ix = (cb);                                                 \
        if (v.y > m) { m = v.y; ix = (cb) + 1; }                            \
        if (v.z > m) { m = v.z; ix = (cb) + 2; }                            \
        if (q < 3 && v.w > m) { m = v.w; ix = (cb) + 3; }

        #pragma unroll
        for (int pass = 0; pass < 2; pass++) {
            const int rowR = g2 + 256 * pass;
            const bool wr  = (rowR < NBOX);
            const int row  = wr ? rowR : (NBOX - 1);

            const float4* rp = (const float4*)(pc5 + (size_t)row * NCLS);
            const float4 v0 = rp[q],      v1 = rp[q + 4],  v2 = rp[q + 8];
            const float4 v3 = rp[q + 12], v4 = rp[q + 16];

            const int c0 = 4 * q;
            float e0, e1, e2, e3, e4;
            float m0, m1, m2, m3, m4;
            int   i0, i1, i2, i3, i4;
            FOLDX (v0, c0,      e0, m0, i0)
            FOLDX (v1, c0 + 16, e1, m1, i1)
            FOLDX (v2, c0 + 32, e2, m2, i2)
            FOLDX (v3, c0 + 48, e3, m3, i3)
            FOLDXL(v4, c0 + 64, e4, m4, i4)

            float e = (e0 + e1) + (e2 + e3) + e4;
            // chunk merge, ascending: strict > keeps lower class on ties
            float best = m0; int bi = i0;
            if (m1 > best) { best = m1; bi = i1; }
            if (m2 > best) { best = m2; bi = i2; }
            if (m3 > best) { best = m3; bi = i3; }
            if (m4 > best) { best = m4; bi = i4; }

            // merge the 4 lanes of the row
            #pragma unroll
            for (int off = 1; off <= 2; off <<= 1) {
                const float e2m = __shfl_xor_sync(FULLM, e,    off);
                const float b2  = __shfl_xor_sync(FULLM, best, off);
                const int   bi2 = __shfl_xor_sync(FULLM, bi,   off);
                e += e2m;
                if (b2 > best || (b2 == best && bi2 < bi)) { best = b2; bi = bi2; }
            }
            if (q == 0 && wr) {
                const float score = __fdividef(__expf(best), e);
                out[OFF_SCORE + b * NBOX + row] = score;
                out[OFF_LAB   + b * NBOX + row] = (float)bi;
                const unsigned p = atomicAdd(&s_cnt[bi], 1u);
                // single 64-bit store: key-hi | label | arrival rank
                s_kp64[row] = ((unsigned long long)(~ord_u(score)) << 32)
                            | ((unsigned long long)(unsigned)bi << 16)
                            | (unsigned long long)p;
            }
        }
#undef FOLDX
#undef FOLDXL
    }
    __syncthreads();

    // ==== Phase 2: geometry build (all threads) + 80-bin scan (warp 0), overlapped
    if (tid < NBOX) {
        // geometry scaled by 3: iou > 0.5  <=>  3*inter > wi + wj (clamps redundant)
        const float w = fmaxf(cw.y, 0.0001f);
        s_geo[tid] = make_float4(3.0f * (cw.x - 0.5f * w), 3.0f * (cw.x + 0.5f * w), w, 0.0f);
    }
    if (wid == 0) {
        const int l = lane;
        const unsigned ca = s_cnt[l];
        const unsigned cb = s_cnt[l + 32];
        const unsigned cc = (l < 16) ? s_cnt[l + 64] : 0u;
        unsigned ia = ca, ib = cb, ic = cc;
        #pragma unroll
        for (int off = 1; off <= 16; off <<= 1) {
            const unsigned ta = __shfl_up_sync(FULLM, ia, off);
            const unsigned tb = __shfl_up_sync(FULLM, ib, off);
            const unsigned tc = __shfl_up_sync(FULLM, ic, off);
            if (l >= off) { ia += ta; ib += tb; ic += tc; }
        }
        const unsigned S0 = __shfl_sync(FULLM, ia, 31);
        const unsigned S1 = __shfl_sync(FULLM, ib, 31);
        s_off[l]      = (int)(ia - ca);
        s_off[l + 32] = (int)(S0 + ib - cb);
        if (l < 16) s_off[l + 64] = (int)(S0 + S1 + ic - cc);
    }
    __syncthreads();

    // ===================== Phase 3: scatter keys into groups =====================
    if (tid < NBOX) {
        const unsigned long long kp = s_kp64[tid];
        const int lab = (int)((kp >> 16) & 0xffffu);
        const int p   = (int)(kp & 0xffffu);
        s_slot[s_off[lab] + p] =
            (kp & 0xffffffff00000000ULL) | (unsigned)tid;
    }
    __syncthreads();

    // ========= Phase 4: warp-parallel per-label NMS (lane = rank) ================
    for (int l = wid; l < NLAB; l += 32) {
        const int g = (int)s_cnt[l];
        if (g == 0) continue;
        const int base = s_off[l];
        if (g <= 32) {
            unsigned long long k =
                (lane < g) ? s_slot[base + lane] : 0xffffffffffffffffULL;
            int rank = 0;
            for (int i = 0; i < g; i++)                      // independent shfls
                rank += (__shfl_sync(FULLM, k, i) < k);
            // physically reorder so lane r holds the rank-r element
            if (lane < g) s_slot[base + rank] = k;
            __syncwarp();
            int idx = 0;
            float4 bx = make_float4(1e30f, -1e30f, 0.0f, 0.0f);   // never overlaps
            if (lane < g) {
                const unsigned long long k2 = s_slot[base + lane];
                idx = (int)(k2 & 0xffffffffu);
                bx  = s_geo[idx];
            }
            // candidate-suppressor bits: i < lane that overlaps me
            unsigned cand = 0;
            for (int i = 0; i < g; i++) {                    // independent shfls
                const float hx1 = __shfl_sync(FULLM, bx.x, i);
                const float hx2 = __shfl_sync(FULLM, bx.y, i);
                const float hw  = __shfl_sync(FULLM, bx.z, i);
                const float t = fminf(hx2, bx.y) - fmaxf(hx1, bx.x);
                if (lane > i && t > hw + bx.z) cand |= 1u << i;
            }
            // greedy resolve: ballots depend only on cand (pipelined); ALU carry
            unsigned sup = 0;
            for (int i = 0; i < g; i++) {
                const unsigned mi = __ballot_sync(FULLM, (cand >> i) & 1u);
                if (!((sup >> i) & 1u)) sup |= mi;
            }
            if (lane < g)
                out[OFF_KEEP + b * NBOX + idx] = ((sup >> lane) & 1u) ? 0.0f : 1.0f;
        } else if (lane == 0) {
            // serial fallback (groups > 32: vanishingly rare)
            unsigned long long sup = 0;
            for (int i = 1; i < g; i++) {
                const unsigned long long kv = s_slot[base + i];
                int j = i - 1;
                while (j >= 0 && s_slot[base + j] > kv) {
                    s_slot[base + j + 1] = s_slot[base + j]; j--;
                }
                s_slot[base + j + 1] = kv;
            }
            for (int aa = 0; aa < g; aa++) {
                const bool kept = (aa >= 64) || !((sup >> aa) & 1ULL);
                const int idx = (int)(s_slot[base + aa] & 0xffffffffu);
                out[OFF_KEEP + b * NBOX + idx] = kept ? 1.0f : 0.0f;
                if (kept) {
                    const float4 ba = s_geo[idx];
                    for (int c = aa + 1; c < g && c < 64; c++) {
                        const int jdx = (int)(s_slot[base + c] & 0xffffffffu);
                        const float4 bc = s_geo[jdx];
                        const float t = fminf(ba.y, bc.y) - fmaxf(ba.x, bc.x);
                        if (t > ba.z + bc.z) sup |= 1ULL << c;
                    }
                }
            }
        }
    }
}

extern "C" void kernel_launch(void* const* d_in, const int* in_sizes, int n_in,
                              void* d_out, int out_size)
{
    const float* boxes_t = (const float*)d_in[0];
    const float* pclass  = (const float*)d_in[1];
    const float* pboxes  = (const float*)d_in[2];
    const float* noise   = (const float*)d_in[3];
    const float* fresh   = (const float*)d_in[4];
    const float* ac      = (const float*)d_in[5];
    const int*   tnow    = (const int*)d_in[6];
    const int*   tnext   = (const int*)d_in[7];
    float* out = (float*)d_out;

    ddet_kernel<<<BATCH + NDDIM, 1024>>>(boxes_t, pclass, pboxes, noise, fresh,
                                         ac, tnow, tnext, out);
}